// round 9
// baseline (speedup 1.0000x reference)
#include <cuda_runtime.h>
#include <cuda_bf16.h>
#include <cstdint>

// Problem constants
#define BB   256   // batch
#define LL   256   // seq len
#define IN_  256   // input dim
#define DD   128   // hidden dim
#define HH   64    // DD/2

// ---------------------------------------------------------------------------
// packed f32x2 helpers (FFMA2)
// ---------------------------------------------------------------------------
__device__ __forceinline__ unsigned long long ffma2(unsigned long long a,
                                                    unsigned long long b,
                                                    unsigned long long c) {
    unsigned long long d;
    asm("fma.rn.f32x2 %0, %1, %2, %3;" : "=l"(d) : "l"(a), "l"(b), "l"(c));
    return d;
}
__device__ __forceinline__ float2 unpack2(unsigned long long v) {
    float2 f;
    asm("mov.b64 {%0, %1}, %2;" : "=f"(f.x), "=f"(f.y) : "l"(v));
    return f;
}
__device__ __forceinline__ unsigned int f2tf32(float f) {
    unsigned int u;
    asm("cvt.rna.tf32.f32 %0, %1;" : "=r"(u) : "f"(f));
    return u;
}

// ---------------------------------------------------------------------------
// Scratch (device globals; no runtime allocation allowed)
// ---------------------------------------------------------------------------
__device__ float g_X[(size_t)BB * LL * 384];  // [b][t][mat*128+d]
__device__ float g_a[(size_t)BB * LL];        // attention gate a[b][t]

// ---------------------------------------------------------------------------
// Kernel A: projection GEMM via tf32 mma.sync (m16n8k8)  (R3 version, best)
// ---------------------------------------------------------------------------
#define PJ_STRIDE 36
extern __shared__ float pj_sm[];

__global__ __launch_bounds__(512, 1) void proj_gemm_tf32(
    const float* __restrict__ x,
    const float* __restrict__ wr, const float* __restrict__ br,
    const float* __restrict__ wz, const float* __restrict__ bz,
    const float* __restrict__ wh, const float* __restrict__ bh,
    float* __restrict__ out)
{
    float* As = pj_sm;                                // [2][128][36]
    float* Bs = pj_sm + 2 * 128 * PJ_STRIDE;          // [2][128][36]

    const int my = blockIdx.y;
    const float* __restrict__ W  = (my == 0) ? wr : (my == 1 ? wz : wh);
    const float* __restrict__ Bv = (my == 0) ? br : (my == 1 ? bz : bh);

    const int tid  = threadIdx.x;
    const int lane = tid & 31;
    const int wid  = tid >> 5;
    const int wm   = wid & 3;
    const int wn   = wid >> 2;
    const int gid  = lane >> 2;
    const int tid4 = lane & 3;
    const int i0   = blockIdx.x * 128;

    const int lr = tid >> 3;
    const int lc = tid & 7;

    float acc[2][4][4];
#pragma unroll
    for (int a = 0; a < 2; a++)
#pragma unroll
        for (int b = 0; b < 4; b++)
#pragma unroll
            for (int c = 0; c < 4; c++) acc[a][b][c] = 0.f;

    float4 sx0, sx1, sw0, sw1;

    {
        const int k0 = 0;
        sx0 = *(const float4*)&x[(size_t)(i0 + lr)      * 256 + k0 + lc * 4];
        sx1 = *(const float4*)&x[(size_t)(i0 + lr + 64) * 256 + k0 + lc * 4];
        sw0 = *(const float4*)&W[(size_t)(lr)      * 256 + k0 + lc * 4];
        sw1 = *(const float4*)&W[(size_t)(lr + 64) * 256 + k0 + lc * 4];
        unsigned int* a0 = (unsigned int*)&As[(size_t)lr * PJ_STRIDE + lc * 4];
        unsigned int* a1 = (unsigned int*)&As[(size_t)(lr + 64) * PJ_STRIDE + lc * 4];
        unsigned int* b0 = (unsigned int*)&Bs[(size_t)lr * PJ_STRIDE + lc * 4];
        unsigned int* b1 = (unsigned int*)&Bs[(size_t)(lr + 64) * PJ_STRIDE + lc * 4];
        a0[0]=f2tf32(sx0.x); a0[1]=f2tf32(sx0.y); a0[2]=f2tf32(sx0.z); a0[3]=f2tf32(sx0.w);
        a1[0]=f2tf32(sx1.x); a1[1]=f2tf32(sx1.y); a1[2]=f2tf32(sx1.z); a1[3]=f2tf32(sx1.w);
        b0[0]=f2tf32(sw0.x); b0[1]=f2tf32(sw0.y); b0[2]=f2tf32(sw0.z); b0[3]=f2tf32(sw0.w);
        b1[0]=f2tf32(sw1.x); b1[1]=f2tf32(sw1.y); b1[2]=f2tf32(sw1.z); b1[3]=f2tf32(sw1.w);
    }
    __syncthreads();

#pragma unroll 1
    for (int t = 0; t < 8; t++) {
        const int cur = t & 1;
        const int nxt = cur ^ 1;
        if (t < 7) {
            const int k0 = (t + 1) * 32;
            sx0 = *(const float4*)&x[(size_t)(i0 + lr)      * 256 + k0 + lc * 4];
            sx1 = *(const float4*)&x[(size_t)(i0 + lr + 64) * 256 + k0 + lc * 4];
            sw0 = *(const float4*)&W[(size_t)(lr)      * 256 + k0 + lc * 4];
            sw1 = *(const float4*)&W[(size_t)(lr + 64) * 256 + k0 + lc * 4];
        }

        const unsigned int* Au = (const unsigned int*)(As + (size_t)cur * 128 * PJ_STRIDE);
        const unsigned int* Bu = (const unsigned int*)(Bs + (size_t)cur * 128 * PJ_STRIDE);

#pragma unroll
        for (int ks = 0; ks < 4; ks++) {
            const int kb = ks * 8;
            unsigned int af[2][4];
#pragma unroll
            for (int mt = 0; mt < 2; mt++) {
                int row = wm * 32 + mt * 16 + gid;
                af[mt][0] = Au[(size_t)row * PJ_STRIDE + kb + tid4];
                af[mt][1] = Au[(size_t)(row + 8) * PJ_STRIDE + kb + tid4];
                af[mt][2] = Au[(size_t)row * PJ_STRIDE + kb + tid4 + 4];
                af[mt][3] = Au[(size_t)(row + 8) * PJ_STRIDE + kb + tid4 + 4];
            }
            unsigned int bf[4][2];
#pragma unroll
            for (int nt = 0; nt < 4; nt++) {
                int col = wn * 32 + nt * 8 + gid;
                bf[nt][0] = Bu[(size_t)col * PJ_STRIDE + kb + tid4];
                bf[nt][1] = Bu[(size_t)col * PJ_STRIDE + kb + tid4 + 4];
            }
#pragma unroll
            for (int mt = 0; mt < 2; mt++)
#pragma unroll
                for (int nt = 0; nt < 4; nt++) {
                    asm volatile(
                        "mma.sync.aligned.m16n8k8.row.col.f32.tf32.tf32.f32 "
                        "{%0,%1,%2,%3}, {%4,%5,%6,%7}, {%8,%9}, {%0,%1,%2,%3};"
                        : "+f"(acc[mt][nt][0]), "+f"(acc[mt][nt][1]),
                          "+f"(acc[mt][nt][2]), "+f"(acc[mt][nt][3])
                        : "r"(af[mt][0]), "r"(af[mt][1]),
                          "r"(af[mt][2]), "r"(af[mt][3]),
                          "r"(bf[nt][0]), "r"(bf[nt][1]));
                }
        }

        if (t < 7) {
            unsigned int* a0 = (unsigned int*)&As[((size_t)nxt * 128 + lr) * PJ_STRIDE + lc * 4];
            unsigned int* a1 = (unsigned int*)&As[((size_t)nxt * 128 + lr + 64) * PJ_STRIDE + lc * 4];
            unsigned int* b0 = (unsigned int*)&Bs[((size_t)nxt * 128 + lr) * PJ_STRIDE + lc * 4];
            unsigned int* b1 = (unsigned int*)&Bs[((size_t)nxt * 128 + lr + 64) * PJ_STRIDE + lc * 4];
            a0[0]=f2tf32(sx0.x); a0[1]=f2tf32(sx0.y); a0[2]=f2tf32(sx0.z); a0[3]=f2tf32(sx0.w);
            a1[0]=f2tf32(sx1.x); a1[1]=f2tf32(sx1.y); a1[2]=f2tf32(sx1.z); a1[3]=f2tf32(sx1.w);
            b0[0]=f2tf32(sw0.x); b0[1]=f2tf32(sw0.y); b0[2]=f2tf32(sw0.z); b0[3]=f2tf32(sw0.w);
            b1[0]=f2tf32(sw1.x); b1[1]=f2tf32(sw1.y); b1[2]=f2tf32(sw1.z); b1[3]=f2tf32(sw1.w);
        }
        __syncthreads();
    }

#pragma unroll
    for (int mt = 0; mt < 2; mt++) {
        int r0 = i0 + wm * 32 + mt * 16 + gid;
#pragma unroll
        for (int nt = 0; nt < 4; nt++) {
            int c0 = wn * 32 + nt * 8 + 2 * tid4;
            float2 bias = *(const float2*)&Bv[c0];
            float* p0 = &out[(size_t)r0 * 384 + my * 128 + c0];
            float* p1 = &out[(size_t)(r0 + 8) * 384 + my * 128 + c0];
            *(float2*)p0 = make_float2(acc[mt][nt][0] + bias.x,
                                       acc[mt][nt][1] + bias.y);
            *(float2*)p1 = make_float2(acc[mt][nt][2] + bias.x,
                                       acc[mt][nt][3] + bias.y);
        }
    }
}

// ---------------------------------------------------------------------------
// Kernel A2: a[b][t] = sigmoid(dot(x[b][t], k1 - k2))
// ---------------------------------------------------------------------------
__global__ __launch_bounds__(256) void a_gate_kernel(
    const float* __restrict__ x, const float* __restrict__ k1k2,
    float* __restrict__ ga)
{
    const int warp = threadIdx.x >> 5, lane = threadIdx.x & 31;
    const int row = blockIdx.x * 8 + warp;
    const float* xr = x + (size_t)row * 256;
    float s = 0.f;
#pragma unroll
    for (int r = 0; r < 2; r++) {
        int k = lane * 4 + r * 128;
        float4 xv = *(const float4*)&xr[k];
        float4 a1 = *(const float4*)&k1k2[k];
        float4 a2 = *(const float4*)&k1k2[256 + k];
        s += xv.x * (a1.x - a2.x) + xv.y * (a1.y - a2.y) +
             xv.z * (a1.z - a2.z) + xv.w * (a1.w - a2.w);
    }
#pragma unroll
    for (int off = 16; off > 0; off >>= 1)
        s += __shfl_xor_sync(0xffffffffu, s, off);
    if (lane == 0) ga[row] = __fdividef(1.f, 1.f + __expf(-s));
}

// ---------------------------------------------------------------------------
// Kernel B v6: ONE batch per CTA, 256 CTAs, 256 threads = (d:128, q:2).
//   2 CTAs co-resident per SM (launch_bounds(256,2), 69 KB smem each):
//   independent per-CTA barriers let one CTA's FFMA2 stream hide the other's
//   serial update/barrier latency (the R5 bottleneck).
//   Per-thread state ~124 regs (96 U + 6 acc + loads) -> fits 128-reg cap.
// ---------------------------------------------------------------------------
#define MHALF 68       // floats per k-half (64 data + 4 pad, bank-disjoint)
#define MPAR  136      // floats per parity
#define BUFS  16456    // history floats (257*64 + 8 pad)

__global__ __launch_bounds__(256, 2) void rnn_kernel(
    const float* __restrict__ gX, const float* __restrict__ ga,
    const int* __restrict__ cor,
    const float* __restrict__ ur, const float* __restrict__ uz,
    const float* __restrict__ uh,
    float* __restrict__ out)
{
    extern __shared__ float sm[];
    float* m_sm   = sm;                    // [2 parity][2 half][68]  272
    float* a_sm   = sm + 272;              // [256]                   256
    int*   cor_sm = (int*)(sm + 528);      // [256]                   256
    float* buf    = sm + 784;              // [BUFS]                  16456

    const int tid = threadIdx.x;
    const int q   = tid & 1;      // k-half
    const int d   = tid >> 1;     // 0..127
    const int b   = blockIdx.x;   // batch
    const int kb  = q * 64;

    // ---- U register cache: row d, k in [kb, kb+64) as 32 pairs/gate ----
    unsigned long long urr[32], uzr[32], uhr[32];
#pragma unroll
    for (int j = 0; j < 32; j++) {
        urr[j] = *(const unsigned long long*)&ur[d * 128 + kb + 2 * j];
        uzr[j] = *(const unsigned long long*)&uz[d * 128 + kb + 2 * j];
        uhr[j] = *(const unsigned long long*)&uh[d * 128 + kb + 2 * j];
    }

    // ---- init ----
    if (tid < 272) m_sm[tid] = 0.f;
    if (tid < 64)  buf[tid] = 0.f;        // t=0 history row
    a_sm[tid]   = ga[(size_t)b * LL + tid];
    cor_sm[tid] = cor[(size_t)b * LL + tid];
    __syncthreads();

    // prefetch X for t=0
    size_t xbase = ((size_t)b * LL) * 384 + d;
    float xr = gX[xbase], xz = gX[xbase + 128], xh = gX[xbase + 256];

    for (int t = 0; t < LL; t++) {
        const int par = t & 1;
        const int np  = par ^ 1;

        // ---- matvec over this thread's k-half ----
        const ulonglong2* mp = (const ulonglong2*)(m_sm + par * MPAR + q * MHALF);
        unsigned long long ar = 0ULL, az = 0ULL, ah = 0ULL;
#pragma unroll
        for (int j = 0; j < 16; j++) {
            ulonglong2 v = mp[j];
            ar = ffma2(urr[2*j],   v.x, ar);
            az = ffma2(uzr[2*j],   v.x, az);
            ah = ffma2(uhr[2*j],   v.x, ah);
            ar = ffma2(urr[2*j+1], v.y, ar);
            az = ffma2(uzr[2*j+1], v.y, az);
            ah = ffma2(uhr[2*j+1], v.y, ah);
        }

        // horizontal add + butterfly (xor 1) -> full-k sums in both lanes
        float2 f;
        f = unpack2(ar); float sr = f.x + f.y;
        f = unpack2(az); float sz = f.x + f.y;
        f = unpack2(ah); float sh = f.x + f.y;
        sr += __shfl_xor_sync(0xffffffffu, sr, 1);
        sz += __shfl_xor_sync(0xffffffffu, sz, 1);
        sh += __shfl_xor_sync(0xffffffffu, sh, 1);

        // ---- nonlinearity + state update (both lanes compute; q==0 stores) ----
        float r  = __fdividef(1.f, 1.f + __expf(-(xr + sr)));
        float z  = __fdividef(1.f, 1.f + __expf(-(xz + sz)));
        float ey = __expf(2.f * (xh + r * sh));
        float hv = 1.f - __fdividef(2.f, ey + 1.f);
        float mv = m_sm[par * MPAR + (d >> 6) * MHALF + (d & 63)];
        float h  = (1.f - z) * mv + z * hv;

        if (q == 0)
            out[(((size_t)b * LL) + t) * DD + d] = h;

        if (t + 1 < LL) {
            // prefetch X for t+1 (consumed after next step's matvec)
            xbase = ((size_t)b * LL + (t + 1)) * 384 + d;
            xr = gX[xbase]; xz = gX[xbase + 128]; xh = gX[xbase + 256];

            if (q == 0) {
                float an = a_sm[t + 1];
                const int mslot = np * MPAR + (d >> 6) * MHALF + (d & 63);
                if (d < HH) {
                    m_sm[mslot] = an * h;
                } else {
                    buf[(t + 1) * 64 + (d - HH)] = h;
                    int cn = cor_sm[t + 1];
                    int ie = (cn == 0) ? (t + 1) : cn;
                    m_sm[mslot] = (1.f - an) * buf[ie * 64 + (d - HH)];
                }
            }
        } else {
            xr = 0.f; xz = 0.f; xh = 0.f;
        }
        __syncthreads();
    }
}

// ---------------------------------------------------------------------------
// launch
// ---------------------------------------------------------------------------
extern "C" void kernel_launch(void* const* d_in, const int* in_sizes, int n_in,
                              void* d_out, int out_size)
{
    (void)in_sizes; (void)n_in; (void)out_size;
    const float* x    = (const float*)d_in[0];
    const int*   cor  = (const int*)d_in[1];
    const float* w_r  = (const float*)d_in[2];
    const float* b_r  = (const float*)d_in[3];
    const float* u_r  = (const float*)d_in[4];
    const float* w_z  = (const float*)d_in[5];
    const float* b_z  = (const float*)d_in[6];
    const float* u_z  = (const float*)d_in[7];
    const float* w_h  = (const float*)d_in[8];
    const float* b_h  = (const float*)d_in[9];
    const float* u_h  = (const float*)d_in[10];
    const float* k1k2 = (const float*)d_in[11];
    float* out = (float*)d_out;

    float* gX; cudaGetSymbolAddress((void**)&gX, g_X);
    float* ga; cudaGetSymbolAddress((void**)&ga, g_a);

    // Kernel A: projections via tf32 tensor cores
    {
        const int smemA = 2 * 2 * 128 * PJ_STRIDE * 4;   // 73728 B
        cudaFuncSetAttribute(proj_gemm_tf32,
                             cudaFuncAttributeMaxDynamicSharedMemorySize, smemA);
        dim3 grid(BB * LL / 128, 3);
        proj_gemm_tf32<<<grid, 512, smemA>>>(x, w_r, b_r, w_z, b_z, w_h, b_h, gX);
    }
    // Kernel A2: attention gate
    a_gate_kernel<<<BB * LL / 8, 256>>>(x, k1k2, ga);

    // Kernel B: recurrence — one batch per CTA, 2 CTAs/SM
    {
        const size_t smemB = (size_t)(784 + BUFS) * sizeof(float);  // 68960 B
        cudaFuncSetAttribute(rnn_kernel,
                             cudaFuncAttributeMaxDynamicSharedMemorySize,
                             (int)smemB);
        rnn_kernel<<<BB, 256, smemB>>>(gX, ga, cor, u_r, u_z, u_h, out);
    }
}

// round 10
// speedup vs baseline: 2.6278x; 2.6278x over previous
#include <cuda_runtime.h>
#include <cuda_bf16.h>
#include <cstdint>

// Problem constants
#define BB   256   // batch
#define LL   256   // seq len
#define IN_  256   // input dim
#define DD   128   // hidden dim
#define HH   64    // DD/2

#define RB    8    // batches per rnn CTA
#define RCTAS (BB / RB)

__device__ __forceinline__ unsigned int f2tf32(float f) {
    unsigned int u;
    asm("cvt.rna.tf32.f32 %0, %1;" : "=r"(u) : "f"(f));
    return u;
}
__device__ __forceinline__ float tf32f(float f) {
    return __uint_as_float(f2tf32(f));
}
__device__ __forceinline__ void mma_tf32(float* acc, const unsigned int* a,
                                         unsigned int b0, unsigned int b1) {
    asm volatile(
        "mma.sync.aligned.m16n8k8.row.col.f32.tf32.tf32.f32 "
        "{%0,%1,%2,%3}, {%4,%5,%6,%7}, {%8,%9}, {%0,%1,%2,%3};"
        : "+f"(acc[0]), "+f"(acc[1]), "+f"(acc[2]), "+f"(acc[3])
        : "r"(a[0]), "r"(a[1]), "r"(a[2]), "r"(a[3]), "r"(b0), "r"(b1));
}

// ---------------------------------------------------------------------------
// Scratch (device globals; no runtime allocation allowed)
// ---------------------------------------------------------------------------
__device__ float g_X[(size_t)BB * LL * 384];        // [b][t][gate*128+d]
__device__ float g_a[(size_t)BB * LL];              // attention gate
__device__ float g_hist[(size_t)BB * 257 * 64];     // history h[:,64:] rows

// ---------------------------------------------------------------------------
// Kernel A: projection GEMM via tf32 mma.sync (m16n8k8)  (R3 version, best)
// ---------------------------------------------------------------------------
#define PJ_STRIDE 36
extern __shared__ float pj_sm[];

__global__ __launch_bounds__(512, 1) void proj_gemm_tf32(
    const float* __restrict__ x,
    const float* __restrict__ wr, const float* __restrict__ br,
    const float* __restrict__ wz, const float* __restrict__ bz,
    const float* __restrict__ wh, const float* __restrict__ bh,
    float* __restrict__ out)
{
    float* As = pj_sm;
    float* Bs = pj_sm + 2 * 128 * PJ_STRIDE;

    const int my = blockIdx.y;
    const float* __restrict__ W  = (my == 0) ? wr : (my == 1 ? wz : wh);
    const float* __restrict__ Bv = (my == 0) ? br : (my == 1 ? bz : bh);

    const int tid  = threadIdx.x;
    const int lane = tid & 31;
    const int wid  = tid >> 5;
    const int wm   = wid & 3;
    const int wn   = wid >> 2;
    const int gid  = lane >> 2;
    const int tid4 = lane & 3;
    const int i0   = blockIdx.x * 128;

    const int lr = tid >> 3;
    const int lc = tid & 7;

    float acc[2][4][4];
#pragma unroll
    for (int a = 0; a < 2; a++)
#pragma unroll
        for (int b = 0; b < 4; b++)
#pragma unroll
            for (int c = 0; c < 4; c++) acc[a][b][c] = 0.f;

    float4 sx0, sx1, sw0, sw1;

    {
        const int k0 = 0;
        sx0 = *(const float4*)&x[(size_t)(i0 + lr)      * 256 + k0 + lc * 4];
        sx1 = *(const float4*)&x[(size_t)(i0 + lr + 64) * 256 + k0 + lc * 4];
        sw0 = *(const float4*)&W[(size_t)(lr)      * 256 + k0 + lc * 4];
        sw1 = *(const float4*)&W[(size_t)(lr + 64) * 256 + k0 + lc * 4];
        unsigned int* a0 = (unsigned int*)&As[(size_t)lr * PJ_STRIDE + lc * 4];
        unsigned int* a1 = (unsigned int*)&As[(size_t)(lr + 64) * PJ_STRIDE + lc * 4];
        unsigned int* b0 = (unsigned int*)&Bs[(size_t)lr * PJ_STRIDE + lc * 4];
        unsigned int* b1 = (unsigned int*)&Bs[(size_t)(lr + 64) * PJ_STRIDE + lc * 4];
        a0[0]=f2tf32(sx0.x); a0[1]=f2tf32(sx0.y); a0[2]=f2tf32(sx0.z); a0[3]=f2tf32(sx0.w);
        a1[0]=f2tf32(sx1.x); a1[1]=f2tf32(sx1.y); a1[2]=f2tf32(sx1.z); a1[3]=f2tf32(sx1.w);
        b0[0]=f2tf32(sw0.x); b0[1]=f2tf32(sw0.y); b0[2]=f2tf32(sw0.z); b0[3]=f2tf32(sw0.w);
        b1[0]=f2tf32(sw1.x); b1[1]=f2tf32(sw1.y); b1[2]=f2tf32(sw1.z); b1[3]=f2tf32(sw1.w);
    }
    __syncthreads();

#pragma unroll 1
    for (int t = 0; t < 8; t++) {
        const int cur = t & 1;
        const int nxt = cur ^ 1;
        if (t < 7) {
            const int k0 = (t + 1) * 32;
            sx0 = *(const float4*)&x[(size_t)(i0 + lr)      * 256 + k0 + lc * 4];
            sx1 = *(const float4*)&x[(size_t)(i0 + lr + 64) * 256 + k0 + lc * 4];
            sw0 = *(const float4*)&W[(size_t)(lr)      * 256 + k0 + lc * 4];
            sw1 = *(const float4*)&W[(size_t)(lr + 64) * 256 + k0 + lc * 4];
        }

        const unsigned int* Au = (const unsigned int*)(As + (size_t)cur * 128 * PJ_STRIDE);
        const unsigned int* Bu = (const unsigned int*)(Bs + (size_t)cur * 128 * PJ_STRIDE);

#pragma unroll
        for (int ks = 0; ks < 4; ks++) {
            const int kb = ks * 8;
            unsigned int af[2][4];
#pragma unroll
            for (int mt = 0; mt < 2; mt++) {
                int row = wm * 32 + mt * 16 + gid;
                af[mt][0] = Au[(size_t)row * PJ_STRIDE + kb + tid4];
                af[mt][1] = Au[(size_t)(row + 8) * PJ_STRIDE + kb + tid4];
                af[mt][2] = Au[(size_t)row * PJ_STRIDE + kb + tid4 + 4];
                af[mt][3] = Au[(size_t)(row + 8) * PJ_STRIDE + kb + tid4 + 4];
            }
            unsigned int bf[4][2];
#pragma unroll
            for (int nt = 0; nt < 4; nt++) {
                int col = wn * 32 + nt * 8 + gid;
                bf[nt][0] = Bu[(size_t)col * PJ_STRIDE + kb + tid4];
                bf[nt][1] = Bu[(size_t)col * PJ_STRIDE + kb + tid4 + 4];
            }
#pragma unroll
            for (int mt = 0; mt < 2; mt++)
#pragma unroll
                for (int nt = 0; nt < 4; nt++)
                    mma_tf32(acc[mt][nt], af[mt], bf[nt][0], bf[nt][1]);
        }

        if (t < 7) {
            unsigned int* a0 = (unsigned int*)&As[((size_t)nxt * 128 + lr) * PJ_STRIDE + lc * 4];
            unsigned int* a1 = (unsigned int*)&As[((size_t)nxt * 128 + lr + 64) * PJ_STRIDE + lc * 4];
            unsigned int* b0 = (unsigned int*)&Bs[((size_t)nxt * 128 + lr) * PJ_STRIDE + lc * 4];
            unsigned int* b1 = (unsigned int*)&Bs[((size_t)nxt * 128 + lr + 64) * PJ_STRIDE + lc * 4];
            a0[0]=f2tf32(sx0.x); a0[1]=f2tf32(sx0.y); a0[2]=f2tf32(sx0.z); a0[3]=f2tf32(sx0.w);
            a1[0]=f2tf32(sx1.x); a1[1]=f2tf32(sx1.y); a1[2]=f2tf32(sx1.z); a1[3]=f2tf32(sx1.w);
            b0[0]=f2tf32(sw0.x); b0[1]=f2tf32(sw0.y); b0[2]=f2tf32(sw0.z); b0[3]=f2tf32(sw0.w);
            b1[0]=f2tf32(sw1.x); b1[1]=f2tf32(sw1.y); b1[2]=f2tf32(sw1.z); b1[3]=f2tf32(sw1.w);
        }
        __syncthreads();
    }

#pragma unroll
    for (int mt = 0; mt < 2; mt++) {
        int r0 = i0 + wm * 32 + mt * 16 + gid;
#pragma unroll
        for (int nt = 0; nt < 4; nt++) {
            int c0 = wn * 32 + nt * 8 + 2 * tid4;
            float2 bias = *(const float2*)&Bv[c0];
            float* p0 = &out[(size_t)r0 * 384 + my * 128 + c0];
            float* p1 = &out[(size_t)(r0 + 8) * 384 + my * 128 + c0];
            *(float2*)p0 = make_float2(acc[mt][nt][0] + bias.x,
                                       acc[mt][nt][1] + bias.y);
            *(float2*)p1 = make_float2(acc[mt][nt][2] + bias.x,
                                       acc[mt][nt][3] + bias.y);
        }
    }
}

// ---------------------------------------------------------------------------
// Kernel A2: a[b][t] = sigmoid(dot(x[b][t], k1 - k2))
// ---------------------------------------------------------------------------
__global__ __launch_bounds__(256) void a_gate_kernel(
    const float* __restrict__ x, const float* __restrict__ k1k2,
    float* __restrict__ ga)
{
    const int warp = threadIdx.x >> 5, lane = threadIdx.x & 31;
    const int row = blockIdx.x * 8 + warp;
    const float* xr = x + (size_t)row * 256;
    float s = 0.f;
#pragma unroll
    for (int r = 0; r < 2; r++) {
        int k = lane * 4 + r * 128;
        float4 xv = *(const float4*)&xr[k];
        float4 a1 = *(const float4*)&k1k2[k];
        float4 a2 = *(const float4*)&k1k2[256 + k];
        s += xv.x * (a1.x - a2.x) + xv.y * (a1.y - a2.y) +
             xv.z * (a1.z - a2.z) + xv.w * (a1.w - a2.w);
    }
#pragma unroll
    for (int off = 16; off > 0; off >>= 1)
        s += __shfl_xor_sync(0xffffffffu, s, off);
    if (lane == 0) ga[row] = __fdividef(1.f, 1.f + __expf(-s));
}

// ---------------------------------------------------------------------------
// Kernel B v7 (tensor-core recurrence): 32 CTAs x 8 batches, 256 threads.
//   Per step: [M=384, N=8, K=128] GEMM via mma.m16n8k8.tf32.
//   U held as A-fragments in registers (8 warps x 48 rows, 192 regs/thread).
//   m split hi/lo (tf32 + tf32 residual): 2 mmas/chunk -> ~22-bit m precision.
//   History buffer in global scratch; gather index cor[t+1] known at step
//   start -> prefetch hides under the matvec; ie==t+1 served from registers.
// ---------------------------------------------------------------------------
#define MSTR 132   // m row stride (floats): banks 4n+k all-distinct for B frags
#define MSEC (RB * MSTR)        // 1056 floats per hi/lo section
#define MPARF (2 * MSEC)        // 2112 floats per parity
#define DSTR 9                  // dump row stride (8 data + 1 pad)

__global__ __launch_bounds__(256, 1) void rnn_tc_kernel(
    const float* __restrict__ gX, const float* __restrict__ ga,
    const int* __restrict__ cor, float* __restrict__ hist,
    const float* __restrict__ ur, const float* __restrict__ uz,
    const float* __restrict__ uh,
    float* __restrict__ out)
{
    extern __shared__ float sm[];
    float* m_sm = sm;                   // [2 par][2 hi/lo][RB][MSTR]  4224
    float* dump = sm + 2 * MPARF;       // [384][DSTR]                 3456
    float* a_sm = dump + 384 * DSTR;    // [RB][256]                   2048
    int* cor_sm = (int*)(a_sm + RB * 256); // [RB][256]                2048

    const int tid  = threadIdx.x;
    const int lane = tid & 31;
    const int w    = tid >> 5;          // warp 0..7, owns M rows [48w, 48w+48)
    const int b0g  = blockIdx.x * RB;

    // ---- load U as A-fragments (once) ----
    // tile mt rows: 48w + 16mt + {lane>>2, lane>>2 + 8}; 16-aligned tiles
    // never cross a gate boundary (multiples of 128).
    unsigned int af[3][16][4];
    {
        const int rbase = w * 48 + (lane >> 2);
        const int c0 = lane & 3;
#pragma unroll
        for (int mt = 0; mt < 3; mt++) {
            const int rA = rbase + mt * 16;
            const int g  = (w * 48 + mt * 16) >> 7;   // gate of this tile
            const float* U = (g == 0) ? ur : (g == 1) ? uz : uh;
            const int dA = rA & 127;
#pragma unroll
            for (int kc = 0; kc < 16; kc++) {
                const int k0 = kc * 8 + c0;
                af[mt][kc][0] = f2tf32(U[dA * 128 + k0]);
                af[mt][kc][1] = f2tf32(U[(dA + 8) * 128 + k0]);
                af[mt][kc][2] = f2tf32(U[dA * 128 + k0 + 4]);
                af[mt][kc][3] = f2tf32(U[(dA + 8) * 128 + k0 + 4]);
            }
        }
    }

    // ---- init ----
    for (int i = tid; i < 2 * MPARF; i += 256) m_sm[i] = 0.f;
    for (int i = tid; i < RB * 256; i += 256) {
        int bb = i >> 8, tt = i & 255;
        a_sm[i]   = ga[(size_t)(b0g + bb) * LL + tt];
        cor_sm[i] = cor[(size_t)(b0g + bb) * LL + tt];
    }
    for (int i = tid; i < RB * 64; i += 256) {
        int bb = i >> 6, dd = i & 63;
        hist[((size_t)(b0g + bb) * 257) * 64 + dd] = 0.f;
    }
    __syncthreads();

    const int ud  = tid >> 1;           // d handled in update phase
    const int ub0 = (tid & 1) * 4;      // batches ub0..ub0+3

    for (int t = 0; t < LL; t++) {
        const int par = t & 1;
        const int np  = par ^ 1;

        // ---- prefetch for the update phase (hidden under the matvec) ----
        float pxr[4], pxz[4], pxh[4], pbuf[4];
        int pie[4];
#pragma unroll
        for (int j = 0; j < 4; j++) {
            const size_t xb = ((size_t)(b0g + ub0 + j) * LL + t) * 384 + ud;
            pxr[j] = gX[xb]; pxz[j] = gX[xb + 128]; pxh[j] = gX[xb + 256];
        }
        if (t + 1 < LL && ud >= HH) {
#pragma unroll
            for (int j = 0; j < 4; j++) {
                const int b = ub0 + j;
                const int cn = cor_sm[b * 256 + t + 1];
                const int ie = (cn == 0) ? (t + 1) : cn;
                pie[j] = ie;
                if (ie <= t)
                    pbuf[j] = hist[((size_t)(b0g + b) * 257 + ie) * 64 + (ud - HH)];
            }
        }

        // ---- matvec: M=384 x N=8 x K=128, hi+lo split ----
        float acc[3][4];
#pragma unroll
        for (int mt = 0; mt < 3; mt++)
#pragma unroll
            for (int j = 0; j < 4; j++) acc[mt][j] = 0.f;

        const unsigned int* mh = (const unsigned int*)(m_sm + par * MPARF);
        const unsigned int* ml = (const unsigned int*)(m_sm + par * MPARF + MSEC);
        const int bk = lane & 3;
        const int bn = lane >> 2;
#pragma unroll
        for (int kc = 0; kc < 16; kc++) {
            const int ba = bn * MSTR + kc * 8 + bk;
            const unsigned int bh0 = mh[ba], bh1 = mh[ba + 4];
            const unsigned int bl0 = ml[ba], bl1 = ml[ba + 4];
#pragma unroll
            for (int mt = 0; mt < 3; mt++) {
                mma_tf32(acc[mt], af[mt][kc], bh0, bh1);
                mma_tf32(acc[mt], af[mt][kc], bl0, bl1);
            }
        }

        // ---- dump accs: dump[row][batch] ----
        {
            const int r0 = w * 48 + (lane >> 2);
            const int c0 = 2 * (lane & 3);
#pragma unroll
            for (int mt = 0; mt < 3; mt++) {
                const int ra = r0 + mt * 16;
                dump[ra * DSTR + c0]           = acc[mt][0];
                dump[ra * DSTR + c0 + 1]       = acc[mt][1];
                dump[(ra + 8) * DSTR + c0]     = acc[mt][2];
                dump[(ra + 8) * DSTR + c0 + 1] = acc[mt][3];
            }
        }
        __syncthreads();

        // ---- elementwise update: thread handles (d=ud, batches ub0..+3) ----
#pragma unroll
        for (int j = 0; j < 4; j++) {
            const int b = ub0 + j;
            const float sr = dump[ud * DSTR + b];
            const float sz = dump[(128 + ud) * DSTR + b];
            const float sh = dump[(256 + ud) * DSTR + b];
            const float r  = __fdividef(1.f, 1.f + __expf(-(pxr[j] + sr)));
            const float z  = __fdividef(1.f, 1.f + __expf(-(pxz[j] + sz)));
            const float ey = __expf(2.f * (pxh[j] + r * sh));
            const float hv = 1.f - __fdividef(2.f, ey + 1.f);
            const float mv = m_sm[par * MPARF + b * MSTR + ud] +
                             m_sm[par * MPARF + MSEC + b * MSTR + ud];
            const float h  = (1.f - z) * mv + z * hv;

            out[((size_t)(b0g + b) * LL + t) * DD + ud] = h;

            if (t + 1 < LL) {
                const float an = a_sm[b * 256 + t + 1];
                float mnew;
                if (ud < HH) {
                    mnew = an * h;
                } else {
                    hist[((size_t)(b0g + b) * 257 + (t + 1)) * 64 + (ud - HH)] = h;
                    const float m2 = (pie[j] == t + 1) ? h : pbuf[j];
                    mnew = (1.f - an) * m2;
                }
                const float hi = tf32f(mnew);
                const float lo = tf32f(mnew - hi);
                m_sm[np * MPARF + b * MSTR + ud]        = hi;
                m_sm[np * MPARF + MSEC + b * MSTR + ud] = lo;
            }
        }
        __syncthreads();
    }
}

// ---------------------------------------------------------------------------
// launch
// ---------------------------------------------------------------------------
extern "C" void kernel_launch(void* const* d_in, const int* in_sizes, int n_in,
                              void* d_out, int out_size)
{
    (void)in_sizes; (void)n_in; (void)out_size;
    const float* x    = (const float*)d_in[0];
    const int*   cor  = (const int*)d_in[1];
    const float* w_r  = (const float*)d_in[2];
    const float* b_r  = (const float*)d_in[3];
    const float* u_r  = (const float*)d_in[4];
    const float* w_z  = (const float*)d_in[5];
    const float* b_z  = (const float*)d_in[6];
    const float* u_z  = (const float*)d_in[7];
    const float* w_h  = (const float*)d_in[8];
    const float* b_h  = (const float*)d_in[9];
    const float* u_h  = (const float*)d_in[10];
    const float* k1k2 = (const float*)d_in[11];
    float* out = (float*)d_out;

    float* gX;   cudaGetSymbolAddress((void**)&gX,   g_X);
    float* ga;   cudaGetSymbolAddress((void**)&ga,   g_a);
    float* hist; cudaGetSymbolAddress((void**)&hist, g_hist);

    // Kernel A: projections via tf32 tensor cores
    {
        const int smemA = 2 * 2 * 128 * PJ_STRIDE * 4;   // 73728 B
        cudaFuncSetAttribute(proj_gemm_tf32,
                             cudaFuncAttributeMaxDynamicSharedMemorySize, smemA);
        dim3 grid(BB * LL / 128, 3);
        proj_gemm_tf32<<<grid, 512, smemA>>>(x, w_r, b_r, w_z, b_z, w_h, b_h, gX);
    }
    // Kernel A2: attention gate
    a_gate_kernel<<<BB * LL / 8, 256>>>(x, k1k2, ga);

    // Kernel B: tensor-core recurrence, 8 batches per CTA
    {
        const int smemB = (2 * MPARF + 384 * DSTR + RB * 256 * 2) * 4; // 47104 B
        cudaFuncSetAttribute(rnn_tc_kernel,
                             cudaFuncAttributeMaxDynamicSharedMemorySize, smemB);
        rnn_tc_kernel<<<RCTAS, 256, smemB>>>(gX, ga, cor, hist,
                                             u_r, u_z, u_h, out);
    }
}

// round 11
// speedup vs baseline: 3.9302x; 1.4956x over previous
#include <cuda_runtime.h>
#include <cuda_bf16.h>
#include <cstdint>

// Problem constants
#define BB   256   // batch
#define LL   256   // seq len
#define IN_  256   // input dim
#define DD   128   // hidden dim
#define HH   64    // DD/2

// ---------------------------------------------------------------------------
// packed f32x2 helpers (FFMA2)
// ---------------------------------------------------------------------------
__device__ __forceinline__ unsigned long long ffma2(unsigned long long a,
                                                    unsigned long long b,
                                                    unsigned long long c) {
    unsigned long long d;
    asm("fma.rn.f32x2 %0, %1, %2, %3;" : "=l"(d) : "l"(a), "l"(b), "l"(c));
    return d;
}
__device__ __forceinline__ float2 unpack2(unsigned long long v) {
    float2 f;
    asm("mov.b64 {%0, %1}, %2;" : "=f"(f.x), "=f"(f.y) : "l"(v));
    return f;
}
__device__ __forceinline__ unsigned int f2tf32(float f) {
    unsigned int u;
    asm("cvt.rna.tf32.f32 %0, %1;" : "=r"(u) : "f"(f));
    return u;
}

// ---------------------------------------------------------------------------
// Scratch (device globals; no runtime allocation allowed)
// ---------------------------------------------------------------------------
__device__ float g_X[(size_t)BB * LL * 384];  // [b][t][gate*128+d]
__device__ float g_a[(size_t)BB * LL];        // attention gate a[b][t]

// ---------------------------------------------------------------------------
// Kernel A: projection GEMM via tf32 mma.sync (m16n8k8)  (R3 version, best)
// ---------------------------------------------------------------------------
#define PJ_STRIDE 36
extern __shared__ float pj_sm[];

__global__ __launch_bounds__(512, 1) void proj_gemm_tf32(
    const float* __restrict__ x,
    const float* __restrict__ wr, const float* __restrict__ br,
    const float* __restrict__ wz, const float* __restrict__ bz,
    const float* __restrict__ wh, const float* __restrict__ bh,
    float* __restrict__ out)
{
    float* As = pj_sm;
    float* Bs = pj_sm + 2 * 128 * PJ_STRIDE;

    const int my = blockIdx.y;
    const float* __restrict__ W  = (my == 0) ? wr : (my == 1 ? wz : wh);
    const float* __restrict__ Bv = (my == 0) ? br : (my == 1 ? bz : bh);

    const int tid  = threadIdx.x;
    const int lane = tid & 31;
    const int wid  = tid >> 5;
    const int wm   = wid & 3;
    const int wn   = wid >> 2;
    const int gid  = lane >> 2;
    const int tid4 = lane & 3;
    const int i0   = blockIdx.x * 128;

    const int lr = tid >> 3;
    const int lc = tid & 7;

    float acc[2][4][4];
#pragma unroll
    for (int a = 0; a < 2; a++)
#pragma unroll
        for (int b = 0; b < 4; b++)
#pragma unroll
            for (int c = 0; c < 4; c++) acc[a][b][c] = 0.f;

    float4 sx0, sx1, sw0, sw1;

    {
        const int k0 = 0;
        sx0 = *(const float4*)&x[(size_t)(i0 + lr)      * 256 + k0 + lc * 4];
        sx1 = *(const float4*)&x[(size_t)(i0 + lr + 64) * 256 + k0 + lc * 4];
        sw0 = *(const float4*)&W[(size_t)(lr)      * 256 + k0 + lc * 4];
        sw1 = *(const float4*)&W[(size_t)(lr + 64) * 256 + k0 + lc * 4];
        unsigned int* a0 = (unsigned int*)&As[(size_t)lr * PJ_STRIDE + lc * 4];
        unsigned int* a1 = (unsigned int*)&As[(size_t)(lr + 64) * PJ_STRIDE + lc * 4];
        unsigned int* b0 = (unsigned int*)&Bs[(size_t)lr * PJ_STRIDE + lc * 4];
        unsigned int* b1 = (unsigned int*)&Bs[(size_t)(lr + 64) * PJ_STRIDE + lc * 4];
        a0[0]=f2tf32(sx0.x); a0[1]=f2tf32(sx0.y); a0[2]=f2tf32(sx0.z); a0[3]=f2tf32(sx0.w);
        a1[0]=f2tf32(sx1.x); a1[1]=f2tf32(sx1.y); a1[2]=f2tf32(sx1.z); a1[3]=f2tf32(sx1.w);
        b0[0]=f2tf32(sw0.x); b0[1]=f2tf32(sw0.y); b0[2]=f2tf32(sw0.z); b0[3]=f2tf32(sw0.w);
        b1[0]=f2tf32(sw1.x); b1[1]=f2tf32(sw1.y); b1[2]=f2tf32(sw1.z); b1[3]=f2tf32(sw1.w);
    }
    __syncthreads();

#pragma unroll 1
    for (int t = 0; t < 8; t++) {
        const int cur = t & 1;
        const int nxt = cur ^ 1;
        if (t < 7) {
            const int k0 = (t + 1) * 32;
            sx0 = *(const float4*)&x[(size_t)(i0 + lr)      * 256 + k0 + lc * 4];
            sx1 = *(const float4*)&x[(size_t)(i0 + lr + 64) * 256 + k0 + lc * 4];
            sw0 = *(const float4*)&W[(size_t)(lr)      * 256 + k0 + lc * 4];
            sw1 = *(const float4*)&W[(size_t)(lr + 64) * 256 + k0 + lc * 4];
        }

        const unsigned int* Au = (const unsigned int*)(As + (size_t)cur * 128 * PJ_STRIDE);
        const unsigned int* Bu = (const unsigned int*)(Bs + (size_t)cur * 128 * PJ_STRIDE);

#pragma unroll
        for (int ks = 0; ks < 4; ks++) {
            const int kb = ks * 8;
            unsigned int af[2][4];
#pragma unroll
            for (int mt = 0; mt < 2; mt++) {
                int row = wm * 32 + mt * 16 + gid;
                af[mt][0] = Au[(size_t)row * PJ_STRIDE + kb + tid4];
                af[mt][1] = Au[(size_t)(row + 8) * PJ_STRIDE + kb + tid4];
                af[mt][2] = Au[(size_t)row * PJ_STRIDE + kb + tid4 + 4];
                af[mt][3] = Au[(size_t)(row + 8) * PJ_STRIDE + kb + tid4 + 4];
            }
            unsigned int bf[4][2];
#pragma unroll
            for (int nt = 0; nt < 4; nt++) {
                int col = wn * 32 + nt * 8 + gid;
                bf[nt][0] = Bu[(size_t)col * PJ_STRIDE + kb + tid4];
                bf[nt][1] = Bu[(size_t)col * PJ_STRIDE + kb + tid4 + 4];
            }
#pragma unroll
            for (int mt = 0; mt < 2; mt++)
#pragma unroll
                for (int nt = 0; nt < 4; nt++) {
                    asm volatile(
                        "mma.sync.aligned.m16n8k8.row.col.f32.tf32.tf32.f32 "
                        "{%0,%1,%2,%3}, {%4,%5,%6,%7}, {%8,%9}, {%0,%1,%2,%3};"
                        : "+f"(acc[mt][nt][0]), "+f"(acc[mt][nt][1]),
                          "+f"(acc[mt][nt][2]), "+f"(acc[mt][nt][3])
                        : "r"(af[mt][0]), "r"(af[mt][1]),
                          "r"(af[mt][2]), "r"(af[mt][3]),
                          "r"(bf[nt][0]), "r"(bf[nt][1]));
                }
        }

        if (t < 7) {
            unsigned int* a0 = (unsigned int*)&As[((size_t)nxt * 128 + lr) * PJ_STRIDE + lc * 4];
            unsigned int* a1 = (unsigned int*)&As[((size_t)nxt * 128 + lr + 64) * PJ_STRIDE + lc * 4];
            unsigned int* b0 = (unsigned int*)&Bs[((size_t)nxt * 128 + lr) * PJ_STRIDE + lc * 4];
            unsigned int* b1 = (unsigned int*)&Bs[((size_t)nxt * 128 + lr + 64) * PJ_STRIDE + lc * 4];
            a0[0]=f2tf32(sx0.x); a0[1]=f2tf32(sx0.y); a0[2]=f2tf32(sx0.z); a0[3]=f2tf32(sx0.w);
            a1[0]=f2tf32(sx1.x); a1[1]=f2tf32(sx1.y); a1[2]=f2tf32(sx1.z); a1[3]=f2tf32(sx1.w);
            b0[0]=f2tf32(sw0.x); b0[1]=f2tf32(sw0.y); b0[2]=f2tf32(sw0.z); b0[3]=f2tf32(sw0.w);
            b1[0]=f2tf32(sw1.x); b1[1]=f2tf32(sw1.y); b1[2]=f2tf32(sw1.z); b1[3]=f2tf32(sw1.w);
        }
        __syncthreads();
    }

#pragma unroll
    for (int mt = 0; mt < 2; mt++) {
        int r0 = i0 + wm * 32 + mt * 16 + gid;
#pragma unroll
        for (int nt = 0; nt < 4; nt++) {
            int c0 = wn * 32 + nt * 8 + 2 * tid4;
            float2 bias = *(const float2*)&Bv[c0];
            float* p0 = &out[(size_t)r0 * 384 + my * 128 + c0];
            float* p1 = &out[(size_t)(r0 + 8) * 384 + my * 128 + c0];
            *(float2*)p0 = make_float2(acc[mt][nt][0] + bias.x,
                                       acc[mt][nt][1] + bias.y);
            *(float2*)p1 = make_float2(acc[mt][nt][2] + bias.x,
                                       acc[mt][nt][3] + bias.y);
        }
    }
}

// ---------------------------------------------------------------------------
// Kernel A2: a[b][t] = sigmoid(dot(x[b][t], k1 - k2))
// ---------------------------------------------------------------------------
__global__ __launch_bounds__(256) void a_gate_kernel(
    const float* __restrict__ x, const float* __restrict__ k1k2,
    float* __restrict__ ga)
{
    const int warp = threadIdx.x >> 5, lane = threadIdx.x & 31;
    const int row = blockIdx.x * 8 + warp;
    const float* xr = x + (size_t)row * 256;
    float s = 0.f;
#pragma unroll
    for (int r = 0; r < 2; r++) {
        int k = lane * 4 + r * 128;
        float4 xv = *(const float4*)&xr[k];
        float4 a1 = *(const float4*)&k1k2[k];
        float4 a2 = *(const float4*)&k1k2[256 + k];
        s += xv.x * (a1.x - a2.x) + xv.y * (a1.y - a2.y) +
             xv.z * (a1.z - a2.z) + xv.w * (a1.w - a2.w);
    }
#pragma unroll
    for (int off = 16; off > 0; off >>= 1)
        s += __shfl_xor_sync(0xffffffffu, s, off);
    if (lane == 0) ga[row] = __fdividef(1.f, 1.f + __expf(-s));
}

// ---------------------------------------------------------------------------
// Kernel B v8: recurrence. 128 CTAs x 2 batches, 512 threads = (d:128, q:4).
//   q = k-quarter. U cache = 48 ull = 96 regs -> 4 warps/SMSP at the 128-reg
//   cap. The two batches' matvecs run SEQUENTIALLY through the SAME 3
//   accumulators (asm memory barrier between them stops ptxas re-interleaving
//   and re-growing register pressure -- the R8 spill cause).
//   Reduction: xor1 batch-exchange, xor2 plain add. One __syncthreads/step.
// ---------------------------------------------------------------------------
#define MQT 36      // floats per quarter (32 data + 4 pad)
#define MB_ 144     // floats per batch   (4*36)
#define MP_ 288     // floats per parity  (2*144)
#define BUFS 16456  // buf batch stride (257*64 + 8 pad)

__global__ __launch_bounds__(512, 1) void rnn_kernel(
    const float* __restrict__ gX, const float* __restrict__ ga,
    const int* __restrict__ cor,
    const float* __restrict__ ur, const float* __restrict__ uz,
    const float* __restrict__ uh,
    float* __restrict__ out)
{
    extern __shared__ float sm[];
    float* m_sm   = sm;                    // [2][2][4][36]          576
    float* a_sm   = sm + 576;              // [2][256]               512
    int*   cor_sm = (int*)(sm + 1088);     // [2][256]               512
    float* buf    = sm + 1600;             // [2][BUFS]              32912

    const int tid  = threadIdx.x;
    const int q    = tid & 3;      // k-quarter
    const int d    = tid >> 2;     // 0..127
    const int beta = q & 1;        // batch this lane finalizes
    const int b0   = blockIdx.x * 2;
    const int kb   = q * 32;

    // ---- U register cache: rows d, k in [kb, kb+32) as 16 pairs/gate ----
    unsigned long long urr[16], uzr[16], uhr[16];
#pragma unroll
    for (int j = 0; j < 16; j++) {
        urr[j] = *(const unsigned long long*)&ur[d * 128 + kb + 2 * j];
        uzr[j] = *(const unsigned long long*)&uz[d * 128 + kb + 2 * j];
        uhr[j] = *(const unsigned long long*)&uh[d * 128 + kb + 2 * j];
    }

    // ---- init ----
    if (tid < 576) m_sm[tid] = 0.f;
    if (tid < 128) buf[(tid >> 6) * BUFS + (tid & 63)] = 0.f;
    {
        int bb = tid >> 8, tt = tid & 255;
        a_sm[tid]   = ga[(size_t)(b0 + bb) * LL + tt];
        cor_sm[tid] = cor[(size_t)(b0 + bb) * LL + tt];
    }
    __syncthreads();

    // prefetch X for t=0, batch beta
    size_t xbase = ((size_t)(b0 + beta) * LL) * 384 + d;
    float xr = gX[xbase], xz = gX[xbase + 128], xh = gX[xbase + 256];

    for (int t = 0; t < LL; t++) {
        const int par = t & 1;
        const int np  = par ^ 1;

        const ulonglong2* p0 = (const ulonglong2*)(m_sm + par * MP_ + q * MQT);
        const ulonglong2* p1 = (const ulonglong2*)(m_sm + par * MP_ + MB_ + q * MQT);

        // ---- batch 0 matvec over quarter [kb,kb+32) ----
        float pr0, pz0, ph0;
        {
            unsigned long long ar = 0ULL, az = 0ULL, ah = 0ULL;
#pragma unroll
            for (int j = 0; j < 8; j++) {
                ulonglong2 v = p0[j];
                ar = ffma2(urr[2*j],   v.x, ar);
                az = ffma2(uzr[2*j],   v.x, az);
                ah = ffma2(uhr[2*j],   v.x, ah);
                ar = ffma2(urr[2*j+1], v.y, ar);
                az = ffma2(uzr[2*j+1], v.y, az);
                ah = ffma2(uhr[2*j+1], v.y, ah);
            }
            float2 f;
            f = unpack2(ar); pr0 = f.x + f.y;
            f = unpack2(az); pz0 = f.x + f.y;
            f = unpack2(ah); ph0 = f.x + f.y;
        }
        asm volatile("" ::: "memory");   // keep batch matvecs sequential

        // ---- batch 1 matvec, reusing accumulator registers ----
        float pr1, pz1, ph1;
        {
            unsigned long long ar = 0ULL, az = 0ULL, ah = 0ULL;
#pragma unroll
            for (int j = 0; j < 8; j++) {
                ulonglong2 v = p1[j];
                ar = ffma2(urr[2*j],   v.x, ar);
                az = ffma2(uzr[2*j],   v.x, az);
                ah = ffma2(uhr[2*j],   v.x, ah);
                ar = ffma2(urr[2*j+1], v.y, ar);
                az = ffma2(uzr[2*j+1], v.y, az);
                ah = ffma2(uhr[2*j+1], v.y, ah);
            }
            float2 f;
            f = unpack2(ar); pr1 = f.x + f.y;
            f = unpack2(az); pz1 = f.x + f.y;
            f = unpack2(ah); ph1 = f.x + f.y;
        }

        // stage 1 (xor 1): keep batch beta, send the other batch's partial
        float sr = (beta ? pr1 : pr0) + __shfl_xor_sync(0xffffffffu, beta ? pr0 : pr1, 1);
        float sz = (beta ? pz1 : pz0) + __shfl_xor_sync(0xffffffffu, beta ? pz0 : pz1, 1);
        float sh = (beta ? ph1 : ph0) + __shfl_xor_sync(0xffffffffu, beta ? ph0 : ph1, 1);
        // stage 2 (xor 2): combine quarter-pairs -> full-k sums for batch beta
        sr += __shfl_xor_sync(0xffffffffu, sr, 2);
        sz += __shfl_xor_sync(0xffffffffu, sz, 2);
        sh += __shfl_xor_sync(0xffffffffu, sh, 2);

        // ---- nonlinearity + state update (lanes q>=2 duplicate compute) ----
        float r  = __fdividef(1.f, 1.f + __expf(-(xr + sr)));
        float z  = __fdividef(1.f, 1.f + __expf(-(xz + sz)));
        float ey = __expf(2.f * (xh + r * sh));
        float hv = 1.f - __fdividef(2.f, ey + 1.f);
        float mv = m_sm[par * MP_ + beta * MB_ + (d >> 5) * MQT + (d & 31)];
        float h  = (1.f - z) * mv + z * hv;

        if (q < 2)
            out[(((size_t)(b0 + beta) * LL) + t) * DD + d] = h;

        if (t + 1 < LL) {
            // prefetch X for t+1 (consumed after next step's matvec)
            xbase = ((size_t)(b0 + beta) * LL + (t + 1)) * 384 + d;
            xr = gX[xbase]; xz = gX[xbase + 128]; xh = gX[xbase + 256];

            if (q < 2) {
                float an = a_sm[beta * 256 + t + 1];
                const int mslot = np * MP_ + beta * MB_ + (d >> 5) * MQT + (d & 31);
                if (d < HH) {
                    m_sm[mslot] = an * h;
                } else {
                    buf[beta * BUFS + (t + 1) * 64 + (d - HH)] = h;
                    int cn = cor_sm[beta * 256 + t + 1];
                    int ie = (cn == 0) ? (t + 1) : cn;
                    m_sm[mslot] = (1.f - an) * buf[beta * BUFS + ie * 64 + (d - HH)];
                }
            }
        }
        __syncthreads();
    }
}

// ---------------------------------------------------------------------------
// launch
// ---------------------------------------------------------------------------
extern "C" void kernel_launch(void* const* d_in, const int* in_sizes, int n_in,
                              void* d_out, int out_size)
{
    (void)in_sizes; (void)n_in; (void)out_size;
    const float* x    = (const float*)d_in[0];
    const int*   cor  = (const int*)d_in[1];
    const float* w_r  = (const float*)d_in[2];
    const float* b_r  = (const float*)d_in[3];
    const float* u_r  = (const float*)d_in[4];
    const float* w_z  = (const float*)d_in[5];
    const float* b_z  = (const float*)d_in[6];
    const float* u_z  = (const float*)d_in[7];
    const float* w_h  = (const float*)d_in[8];
    const float* b_h  = (const float*)d_in[9];
    const float* u_h  = (const float*)d_in[10];
    const float* k1k2 = (const float*)d_in[11];
    float* out = (float*)d_out;

    float* gX; cudaGetSymbolAddress((void**)&gX, g_X);
    float* ga; cudaGetSymbolAddress((void**)&ga, g_a);

    // Kernel A: projections via tf32 tensor cores
    {
        const int smemA = 2 * 2 * 128 * PJ_STRIDE * 4;   // 73728 B
        cudaFuncSetAttribute(proj_gemm_tf32,
                             cudaFuncAttributeMaxDynamicSharedMemorySize, smemA);
        dim3 grid(BB * LL / 128, 3);
        proj_gemm_tf32<<<grid, 512, smemA>>>(x, w_r, b_r, w_z, b_z, w_h, b_h, gX);
    }
    // Kernel A2: attention gate
    a_gate_kernel<<<BB * LL / 8, 256>>>(x, k1k2, ga);

    // Kernel B: recurrence
    {
        const size_t smemB = (size_t)(1600 + 2 * BUFS) * sizeof(float); // 138048 B
        cudaFuncSetAttribute(rnn_kernel,
                             cudaFuncAttributeMaxDynamicSharedMemorySize,
                             (int)smemB);
        rnn_kernel<<<128, 512, smemB>>>(gX, ga, cor, u_r, u_z, u_h, out);
    }
}

// round 13
// speedup vs baseline: 4.0512x; 1.0308x over previous
#include <cuda_runtime.h>
#include <cuda_bf16.h>
#include <cstdint>

// Problem constants
#define BB   256   // batch
#define LL   256   // seq len
#define IN_  256   // input dim
#define DD   128   // hidden dim
#define HH   64    // DD/2

// ---------------------------------------------------------------------------
// packed f32x2 helpers (FFMA2)
// ---------------------------------------------------------------------------
__device__ __forceinline__ unsigned long long ffma2(unsigned long long a,
                                                    unsigned long long b,
                                                    unsigned long long c) {
    unsigned long long d;
    asm("fma.rn.f32x2 %0, %1, %2, %3;" : "=l"(d) : "l"(a), "l"(b), "l"(c));
    return d;
}
__device__ __forceinline__ float2 unpack2(unsigned long long v) {
    float2 f;
    asm("mov.b64 {%0, %1}, %2;" : "=f"(f.x), "=f"(f.y) : "l"(v));
    return f;
}
__device__ __forceinline__ unsigned int f2tf32(float f) {
    unsigned int u;
    asm("cvt.rna.tf32.f32 %0, %1;" : "=r"(u) : "f"(f));
    return u;
}

// ---------------------------------------------------------------------------
// Scratch (device globals; no runtime allocation allowed)
// ---------------------------------------------------------------------------
__device__ float g_X[(size_t)BB * LL * 384];  // [b][t][gate*128+d]
__device__ float g_a[(size_t)BB * LL];        // attention gate a[b][t]

// ---------------------------------------------------------------------------
// Kernel A: projection GEMM via tf32 mma.sync (m16n8k8).
//   ROW-MAJOR smem tiles [row][k] (stride 36): tile stores are one STS.128
//   per thread per row instead of 16 scattered STS.32 (same values, same
//   frag mapping, conflict-free by the same bank permutation).
// ---------------------------------------------------------------------------
#define PJ_STRIDE 36
#define PJ_TILE  (128 * PJ_STRIDE)
extern __shared__ float pj_sm[];

__global__ __launch_bounds__(512, 1) void proj_gemm_tf32(
    const float* __restrict__ x,
    const float* __restrict__ wr, const float* __restrict__ br,
    const float* __restrict__ wz, const float* __restrict__ bz,
    const float* __restrict__ wh, const float* __restrict__ bh,
    float* __restrict__ out)
{
    float* As = pj_sm;                       // [2][128][36]
    float* Bs = pj_sm + 2 * PJ_TILE;         // [2][128][36]

    const int my = blockIdx.y;
    const float* __restrict__ W  = (my == 0) ? wr : (my == 1 ? wz : wh);
    const float* __restrict__ Bv = (my == 0) ? br : (my == 1 ? bz : bh);

    const int tid  = threadIdx.x;
    const int lane = tid & 31;
    const int wid  = tid >> 5;
    const int wm   = wid & 3;
    const int wn   = wid >> 2;
    const int gid  = lane >> 2;
    const int tid4 = lane & 3;
    const int i0   = blockIdx.x * 128;

    const int lr = tid >> 3;      // 0..63 (row in 64-row half)
    const int lc = tid & 7;       // 0..7  (k group of 4)

    float acc[2][4][4];
#pragma unroll
    for (int a = 0; a < 2; a++)
#pragma unroll
        for (int b = 0; b < 4; b++)
#pragma unroll
            for (int c = 0; c < 4; c++) acc[a][b][c] = 0.f;

    float4 sx0, sx1, sw0, sw1;

    // prologue: load + convert + store tile 0 (row-major, STS.128)
    {
        const int k0 = 0;
        sx0 = *(const float4*)&x[(size_t)(i0 + lr)      * 256 + k0 + lc * 4];
        sx1 = *(const float4*)&x[(size_t)(i0 + lr + 64) * 256 + k0 + lc * 4];
        sw0 = *(const float4*)&W[(size_t)(lr)      * 256 + k0 + lc * 4];
        sw1 = *(const float4*)&W[(size_t)(lr + 64) * 256 + k0 + lc * 4];
        *(uint4*)&As[lr * PJ_STRIDE + lc * 4] =
            make_uint4(f2tf32(sx0.x), f2tf32(sx0.y), f2tf32(sx0.z), f2tf32(sx0.w));
        *(uint4*)&As[(lr + 64) * PJ_STRIDE + lc * 4] =
            make_uint4(f2tf32(sx1.x), f2tf32(sx1.y), f2tf32(sx1.z), f2tf32(sx1.w));
        *(uint4*)&Bs[lr * PJ_STRIDE + lc * 4] =
            make_uint4(f2tf32(sw0.x), f2tf32(sw0.y), f2tf32(sw0.z), f2tf32(sw0.w));
        *(uint4*)&Bs[(lr + 64) * PJ_STRIDE + lc * 4] =
            make_uint4(f2tf32(sw1.x), f2tf32(sw1.y), f2tf32(sw1.z), f2tf32(sw1.w));
    }
    __syncthreads();

#pragma unroll 1
    for (int t = 0; t < 8; t++) {
        const int cur = t & 1;
        const int nxt = cur ^ 1;
        if (t < 7) {
            const int k0 = (t + 1) * 32;
            sx0 = *(const float4*)&x[(size_t)(i0 + lr)      * 256 + k0 + lc * 4];
            sx1 = *(const float4*)&x[(size_t)(i0 + lr + 64) * 256 + k0 + lc * 4];
            sw0 = *(const float4*)&W[(size_t)(lr)      * 256 + k0 + lc * 4];
            sw1 = *(const float4*)&W[(size_t)(lr + 64) * 256 + k0 + lc * 4];
        }

        const unsigned int* Au = (const unsigned int*)(As + cur * PJ_TILE);
        const unsigned int* Bu = (const unsigned int*)(Bs + cur * PJ_TILE);

#pragma unroll
        for (int ks = 0; ks < 4; ks++) {
            const int kb = ks * 8;
            unsigned int af[2][4];
#pragma unroll
            for (int mt = 0; mt < 2; mt++) {
                int row = wm * 32 + mt * 16 + gid;
                af[mt][0] = Au[row * PJ_STRIDE + kb + tid4];
                af[mt][1] = Au[(row + 8) * PJ_STRIDE + kb + tid4];
                af[mt][2] = Au[row * PJ_STRIDE + kb + tid4 + 4];
                af[mt][3] = Au[(row + 8) * PJ_STRIDE + kb + tid4 + 4];
            }
            unsigned int bf[4][2];
#pragma unroll
            for (int nt = 0; nt < 4; nt++) {
                int col = wn * 32 + nt * 8 + gid;
                bf[nt][0] = Bu[col * PJ_STRIDE + kb + tid4];
                bf[nt][1] = Bu[col * PJ_STRIDE + kb + tid4 + 4];
            }
#pragma unroll
            for (int mt = 0; mt < 2; mt++)
#pragma unroll
                for (int nt = 0; nt < 4; nt++) {
                    asm volatile(
                        "mma.sync.aligned.m16n8k8.row.col.f32.tf32.tf32.f32 "
                        "{%0,%1,%2,%3}, {%4,%5,%6,%7}, {%8,%9}, {%0,%1,%2,%3};"
                        : "+f"(acc[mt][nt][0]), "+f"(acc[mt][nt][1]),
                          "+f"(acc[mt][nt][2]), "+f"(acc[mt][nt][3])
                        : "r"(af[mt][0]), "r"(af[mt][1]),
                          "r"(af[mt][2]), "r"(af[mt][3]),
                          "r"(bf[nt][0]), "r"(bf[nt][1]));
                }
        }

        if (t < 7) {
            float* Ad = As + nxt * PJ_TILE;
            float* Bd = Bs + nxt * PJ_TILE;
            *(uint4*)&Ad[lr * PJ_STRIDE + lc * 4] =
                make_uint4(f2tf32(sx0.x), f2tf32(sx0.y), f2tf32(sx0.z), f2tf32(sx0.w));
            *(uint4*)&Ad[(lr + 64) * PJ_STRIDE + lc * 4] =
                make_uint4(f2tf32(sx1.x), f2tf32(sx1.y), f2tf32(sx1.z), f2tf32(sx1.w));
            *(uint4*)&Bd[lr * PJ_STRIDE + lc * 4] =
                make_uint4(f2tf32(sw0.x), f2tf32(sw0.y), f2tf32(sw0.z), f2tf32(sw0.w));
            *(uint4*)&Bd[(lr + 64) * PJ_STRIDE + lc * 4] =
                make_uint4(f2tf32(sw1.x), f2tf32(sw1.y), f2tf32(sw1.z), f2tf32(sw1.w));
        }
        __syncthreads();
    }

    // epilogue: bias + store
#pragma unroll
    for (int mt = 0; mt < 2; mt++) {
        int r0 = i0 + wm * 32 + mt * 16 + gid;
#pragma unroll
        for (int nt = 0; nt < 4; nt++) {
            int c0 = wn * 32 + nt * 8 + 2 * tid4;
            float2 bias = *(const float2*)&Bv[c0];
            float* p0 = &out[(size_t)r0 * 384 + my * 128 + c0];
            float* p1 = &out[(size_t)(r0 + 8) * 384 + my * 128 + c0];
            *(float2*)p0 = make_float2(acc[mt][nt][0] + bias.x,
                                       acc[mt][nt][1] + bias.y);
            *(float2*)p1 = make_float2(acc[mt][nt][2] + bias.x,
                                       acc[mt][nt][3] + bias.y);
        }
    }
}

// ---------------------------------------------------------------------------
// Kernel A2: a[b][t] = sigmoid(dot(x[b][t], k1 - k2))
// ---------------------------------------------------------------------------
__global__ __launch_bounds__(256) void a_gate_kernel(
    const float* __restrict__ x, const float* __restrict__ k1k2,
    float* __restrict__ ga)
{
    const int warp = threadIdx.x >> 5, lane = threadIdx.x & 31;
    const int row = blockIdx.x * 8 + warp;
    const float* xr = x + (size_t)row * 256;
    float s = 0.f;
#pragma unroll
    for (int r = 0; r < 2; r++) {
        int k = lane * 4 + r * 128;
        float4 xv = *(const float4*)&xr[k];
        float4 a1 = *(const float4*)&k1k2[k];
        float4 a2 = *(const float4*)&k1k2[256 + k];
        s += xv.x * (a1.x - a2.x) + xv.y * (a1.y - a2.y) +
             xv.z * (a1.z - a2.z) + xv.w * (a1.w - a2.w);
    }
#pragma unroll
    for (int off = 16; off > 0; off >>= 1)
        s += __shfl_xor_sync(0xffffffffu, s, off);
    if (lane == 0) ga[row] = __fdividef(1.f, 1.f + __expf(-s));
}

// ---------------------------------------------------------------------------
// Kernel B (R5's v4, best measured rnn: 299 us): 128 CTAs x 2 batches,
//   256 threads = (d:128, q:2). U register-resident (192 regs), direct
//   ulonglong2 m loads, 68-float padded halves (bank-disjoint broadcasts),
//   3 shuffles/step, m double-buffered by parity -> one barrier/step.
// ---------------------------------------------------------------------------
#define MPAR 272   // floats per parity
#define MBAT 136   // floats per batch
#define MHALF 68   // floats per k-half (64 data + 4 pad)

__global__ __launch_bounds__(256, 1) void rnn_kernel(
    const float* __restrict__ gX, const float* __restrict__ ga,
    const int* __restrict__ cor,
    const float* __restrict__ ur, const float* __restrict__ uz,
    const float* __restrict__ uh,
    float* __restrict__ out)
{
    extern __shared__ float sm[];
    float* m_sm   = sm;                    // [2 parity][2 b][2 half][68]  544
    float* a_sm   = sm + 544;              // [2][256]               512
    int*   cor_sm = (int*)(sm + 1056);     // [2][256]               512
    float* buf    = sm + 1568;             // [2][257][64]           32896

    const int tid = threadIdx.x;
    const int q   = tid & 1;      // k-half; also batch assignment for update
    const int d   = tid >> 1;     // 0..127
    const int b0  = blockIdx.x * 2;
    const int kb  = q * 64;

    // ---- U register cache: rows d of u_r/u_z/u_h, k in [kb, kb+64) ----
    unsigned long long urr[32], uzr[32], uhr[32];
#pragma unroll
    for (int j = 0; j < 32; j++) {
        urr[j] = *(const unsigned long long*)&ur[d * 128 + kb + 2 * j];
        uzr[j] = *(const unsigned long long*)&uz[d * 128 + kb + 2 * j];
        uhr[j] = *(const unsigned long long*)&uh[d * 128 + kb + 2 * j];
    }

    // ---- init ----
#pragma unroll
    for (int i = tid; i < 544; i += 256) m_sm[i] = 0.f;
    if (tid < 128) {
        int bb = tid >> 6;
        buf[bb * 16448 + (tid & 63)] = 0.f;
    }
#pragma unroll
    for (int i = tid; i < 512; i += 256) {
        int bb = i >> 8, tt = i & 255;
        a_sm[i]   = ga[(size_t)(b0 + bb) * LL + tt];
        cor_sm[i] = cor[(size_t)(b0 + bb) * LL + tt];
    }
    __syncthreads();

    // prefetch X for t=0, batch q
    size_t xbase = ((size_t)(b0 + q) * LL) * 384 + d;
    float xr = gX[xbase], xz = gX[xbase + 128], xh = gX[xbase + 256];

    for (int t = 0; t < LL; t++) {
        const int par = t & 1;
        const int np  = par ^ 1;

        // ---- matvec over k-half [kb,kb+64), both batches ----
        const ulonglong2* p0 =
            (const ulonglong2*)(m_sm + par * MPAR + q * MHALF);           // b0
        const ulonglong2* p1 =
            (const ulonglong2*)(m_sm + par * MPAR + MBAT + q * MHALF);    // b1
        unsigned long long ar0 = 0ULL, az0 = 0ULL, ah0 = 0ULL;
        unsigned long long ar1 = 0ULL, az1 = 0ULL, ah1 = 0ULL;
#pragma unroll
        for (int j = 0; j < 16; j++) {
            ulonglong2 v0 = p0[j];
            ulonglong2 v1 = p1[j];
            ar0 = ffma2(urr[2*j],   v0.x, ar0);
            az0 = ffma2(uzr[2*j],   v0.x, az0);
            ah0 = ffma2(uhr[2*j],   v0.x, ah0);
            ar1 = ffma2(urr[2*j],   v1.x, ar1);
            az1 = ffma2(uzr[2*j],   v1.x, az1);
            ah1 = ffma2(uhr[2*j],   v1.x, ah1);
            ar0 = ffma2(urr[2*j+1], v0.y, ar0);
            az0 = ffma2(uzr[2*j+1], v0.y, az0);
            ah0 = ffma2(uhr[2*j+1], v0.y, ah0);
            ar1 = ffma2(urr[2*j+1], v1.y, ar1);
            az1 = ffma2(uzr[2*j+1], v1.y, az1);
            ah1 = ffma2(uhr[2*j+1], v1.y, ah1);
        }

        // horizontal add; exchange: send partner the batch it keeps
        float2 f;
        f = unpack2(ar0); float sr0 = f.x + f.y;
        f = unpack2(az0); float sz0 = f.x + f.y;
        f = unpack2(ah0); float sh0 = f.x + f.y;
        f = unpack2(ar1); float sr1 = f.x + f.y;
        f = unpack2(az1); float sz1 = f.x + f.y;
        f = unpack2(ah1); float sh1 = f.x + f.y;

        float sr = (q ? sr1 : sr0) + __shfl_xor_sync(0xffffffffu, q ? sr0 : sr1, 1);
        float sz = (q ? sz1 : sz0) + __shfl_xor_sync(0xffffffffu, q ? sz0 : sz1, 1);
        float sh = (q ? sh1 : sh0) + __shfl_xor_sync(0xffffffffu, q ? sh0 : sh1, 1);

        // ---- nonlinearity + state update (all 256 threads) ----
        float r  = __fdividef(1.f, 1.f + __expf(-(xr + sr)));
        float z  = __fdividef(1.f, 1.f + __expf(-(xz + sz)));
        float ey = __expf(2.f * (xh + r * sh));
        float hv = 1.f - __fdividef(2.f, ey + 1.f);
        float mv = m_sm[par * MPAR + q * MBAT + (d < HH ? d : MHALF + d - HH)];
        float h  = (1.f - z) * mv + z * hv;

        out[(((size_t)(b0 + q) * LL) + t) * DD + d] = h;

        if (t + 1 < LL) {
            // prefetch X for t+1 (consumed after next step's matvec)
            xbase = ((size_t)(b0 + q) * LL + (t + 1)) * 384 + d;
            xr = gX[xbase]; xz = gX[xbase + 128]; xh = gX[xbase + 256];

            float an = a_sm[q * 256 + t + 1];
            if (d < HH) {
                m_sm[np * MPAR + q * MBAT + d] = an * h;
            } else {
                buf[q * 16448 + (t + 1) * 64 + (d - HH)] = h;
                int cn = cor_sm[q * 256 + t + 1];
                int ie = (cn == 0) ? (t + 1) : cn;
                m_sm[np * MPAR + q * MBAT + MHALF + (d - HH)] =
                    (1.f - an) * buf[q * 16448 + ie * 64 + (d - HH)];
            }
        }
        __syncthreads();
    }
}

// ---------------------------------------------------------------------------
// launch
// ---------------------------------------------------------------------------
extern "C" void kernel_launch(void* const* d_in, const int* in_sizes, int n_in,
                              void* d_out, int out_size)
{
    (void)in_sizes; (void)n_in; (void)out_size;
    const float* x    = (const float*)d_in[0];
    const int*   cor  = (const int*)d_in[1];
    const float* w_r  = (const float*)d_in[2];
    const float* b_r  = (const float*)d_in[3];
    const float* u_r  = (const float*)d_in[4];
    const float* w_z  = (const float*)d_in[5];
    const float* b_z  = (const float*)d_in[6];
    const float* u_z  = (const float*)d_in[7];
    const float* w_h  = (const float*)d_in[8];
    const float* b_h  = (const float*)d_in[9];
    const float* u_h  = (const float*)d_in[10];
    const float* k1k2 = (const float*)d_in[11];
    float* out = (float*)d_out;

    float* gX; cudaGetSymbolAddress((void**)&gX, g_X);
    float* ga; cudaGetSymbolAddress((void**)&ga, g_a);

    // Kernel A: projections via tf32 tensor cores (row-major smem tiles)
    {
        const int smemA = 4 * PJ_TILE * 4;               // 73728 B
        cudaFuncSetAttribute(proj_gemm_tf32,
                             cudaFuncAttributeMaxDynamicSharedMemorySize, smemA);
        dim3 grid(BB * LL / 128, 3);
        proj_gemm_tf32<<<grid, 512, smemA>>>(x, w_r, b_r, w_z, b_z, w_h, b_h, gX);
    }
    // Kernel A2: attention gate
    a_gate_kernel<<<BB * LL / 8, 256>>>(x, k1k2, ga);

    // Kernel B: recurrence (best measured variant)
    {
        const size_t smemB = (size_t)(544 + 512 + 512 + 2 * 257 * 64)
                             * sizeof(float);            // 137856 B
        cudaFuncSetAttribute(rnn_kernel,
                             cudaFuncAttributeMaxDynamicSharedMemorySize,
                             (int)smemB);
        rnn_kernel<<<128, 256, smemB>>>(gX, ga, cor, u_r, u_z, u_h, out);
    }
}

// round 16
// speedup vs baseline: 4.2159x; 1.0407x over previous
#include <cuda_runtime.h>
#include <cuda_bf16.h>
#include <cstdint>

// Problem constants
#define BB   256   // batch
#define LL   256   // seq len
#define IN_  256   // input dim
#define DD   128   // hidden dim
#define HH   64    // DD/2

// ---------------------------------------------------------------------------
// packed f32x2 helpers (FFMA2)
// ---------------------------------------------------------------------------
__device__ __forceinline__ unsigned long long ffma2(unsigned long long a,
                                                    unsigned long long b,
                                                    unsigned long long c) {
    unsigned long long d;
    asm("fma.rn.f32x2 %0, %1, %2, %3;" : "=l"(d) : "l"(a), "l"(b), "l"(c));
    return d;
}
__device__ __forceinline__ float2 unpack2(unsigned long long v) {
    float2 f;
    asm("mov.b64 {%0, %1}, %2;" : "=f"(f.x), "=f"(f.y) : "l"(v));
    return f;
}
__device__ __forceinline__ unsigned int f2tf32(float f) {
    unsigned int u;
    asm("cvt.rna.tf32.f32 %0, %1;" : "=r"(u) : "f"(f));
    return u;
}

// ---------------------------------------------------------------------------
// Scratch (device globals; no runtime allocation allowed)
// ---------------------------------------------------------------------------
__device__ float g_X[(size_t)BB * LL * 384];  // [b][t][gate*128+d]
__device__ float g_a[(size_t)BB * LL];        // attention gate a[b][t]

// ---------------------------------------------------------------------------
// Kernel A v3: projection GEMM, tf32 mma.sync, 64x64 WARP TILES.
//   BM=256, BN=128, BK=32; 256 threads = 8 warps (wm:4 x wn:2).
//   Frag reuse 2x better than 32x32 tiles -> L1 crossbar per mma halves
//   -> tensor-bound. Row-major smem [row][k] stride 36, double-buffered.
// ---------------------------------------------------------------------------
#define PJ_STRIDE 36
#define PJ_ATILE (256 * PJ_STRIDE)    // floats per A buffer
#define PJ_BTILE (128 * PJ_STRIDE)    // floats per B buffer
extern __shared__ float pj_sm[];

__global__ __launch_bounds__(256, 1) void proj_gemm_tf32(
    const float* __restrict__ x,
    const float* __restrict__ wr, const float* __restrict__ br,
    const float* __restrict__ wz, const float* __restrict__ bz,
    const float* __restrict__ wh, const float* __restrict__ bh,
    float* __restrict__ out)
{
    float* As = pj_sm;                          // [2][256][36]
    float* Bs = pj_sm + 2 * PJ_ATILE;           // [2][128][36]

    const int my = blockIdx.y;
    const float* __restrict__ W  = (my == 0) ? wr : (my == 1 ? wz : wh);
    const float* __restrict__ Bv = (my == 0) ? br : (my == 1 ? bz : bh);

    const int tid  = threadIdx.x;
    const int lane = tid & 31;
    const int wid  = tid >> 5;
    const int wm   = wid & 3;        // 0..3 -> 64-row slab
    const int wn   = wid >> 2;       // 0..1 -> 64-col slab
    const int gid  = lane >> 2;      // 0..7
    const int tid4 = lane & 3;       // 0..3
    const int i0   = blockIdx.x * 256;

    const int lr = tid >> 3;         // 0..31 (base row)
    const int lc = tid & 7;          // 0..7  (k float4 group)

    float acc[4][8][4];
#pragma unroll
    for (int a = 0; a < 4; a++)
#pragma unroll
        for (int b = 0; b < 8; b++)
#pragma unroll
            for (int c = 0; c < 4; c++) acc[a][b][c] = 0.f;

    float4 sa[8], sb[4];

    // prologue: load + convert + store tile 0
    {
        const int k0 = 0;
#pragma unroll
        for (int rr = 0; rr < 8; rr++)
            sa[rr] = *(const float4*)&x[(size_t)(i0 + lr + rr * 32) * 256 + k0 + lc * 4];
#pragma unroll
        for (int rr = 0; rr < 4; rr++)
            sb[rr] = *(const float4*)&W[(size_t)(lr + rr * 32) * 256 + k0 + lc * 4];
#pragma unroll
        for (int rr = 0; rr < 8; rr++)
            *(uint4*)&As[(lr + rr * 32) * PJ_STRIDE + lc * 4] =
                make_uint4(f2tf32(sa[rr].x), f2tf32(sa[rr].y),
                           f2tf32(sa[rr].z), f2tf32(sa[rr].w));
#pragma unroll
        for (int rr = 0; rr < 4; rr++)
            *(uint4*)&Bs[(lr + rr * 32) * PJ_STRIDE + lc * 4] =
                make_uint4(f2tf32(sb[rr].x), f2tf32(sb[rr].y),
                           f2tf32(sb[rr].z), f2tf32(sb[rr].w));
    }
    __syncthreads();

#pragma unroll 1
    for (int t = 0; t < 8; t++) {
        const int cur = t & 1;
        const int nxt = cur ^ 1;
        if (t < 7) {
            const int k0 = (t + 1) * 32;
#pragma unroll
            for (int rr = 0; rr < 8; rr++)
                sa[rr] = *(const float4*)&x[(size_t)(i0 + lr + rr * 32) * 256 + k0 + lc * 4];
#pragma unroll
            for (int rr = 0; rr < 4; rr++)
                sb[rr] = *(const float4*)&W[(size_t)(lr + rr * 32) * 256 + k0 + lc * 4];
        }

        const unsigned int* Au = (const unsigned int*)(As + cur * PJ_ATILE);
        const unsigned int* Bu = (const unsigned int*)(Bs + cur * PJ_BTILE);

#pragma unroll
        for (int ks = 0; ks < 4; ks++) {
            const int kb = ks * 8;
            unsigned int af[4][4];
#pragma unroll
            for (int mt = 0; mt < 4; mt++) {
                int row = wm * 64 + mt * 16 + gid;
                af[mt][0] = Au[row * PJ_STRIDE + kb + tid4];
                af[mt][1] = Au[(row + 8) * PJ_STRIDE + kb + tid4];
                af[mt][2] = Au[row * PJ_STRIDE + kb + tid4 + 4];
                af[mt][3] = Au[(row + 8) * PJ_STRIDE + kb + tid4 + 4];
            }
            unsigned int bf[8][2];
#pragma unroll
            for (int nt = 0; nt < 8; nt++) {
                int col = wn * 64 + nt * 8 + gid;
                bf[nt][0] = Bu[col * PJ_STRIDE + kb + tid4];
                bf[nt][1] = Bu[col * PJ_STRIDE + kb + tid4 + 4];
            }
#pragma unroll
            for (int mt = 0; mt < 4; mt++)
#pragma unroll
                for (int nt = 0; nt < 8; nt++) {
                    asm volatile(
                        "mma.sync.aligned.m16n8k8.row.col.f32.tf32.tf32.f32 "
                        "{%0,%1,%2,%3}, {%4,%5,%6,%7}, {%8,%9}, {%0,%1,%2,%3};"
                        : "+f"(acc[mt][nt][0]), "+f"(acc[mt][nt][1]),
                          "+f"(acc[mt][nt][2]), "+f"(acc[mt][nt][3])
                        : "r"(af[mt][0]), "r"(af[mt][1]),
                          "r"(af[mt][2]), "r"(af[mt][3]),
                          "r"(bf[nt][0]), "r"(bf[nt][1]));
                }
        }

        if (t < 7) {
            float* Ad = As + nxt * PJ_ATILE;
            float* Bd = Bs + nxt * PJ_BTILE;
#pragma unroll
            for (int rr = 0; rr < 8; rr++)
                *(uint4*)&Ad[(lr + rr * 32) * PJ_STRIDE + lc * 4] =
                    make_uint4(f2tf32(sa[rr].x), f2tf32(sa[rr].y),
                               f2tf32(sa[rr].z), f2tf32(sa[rr].w));
#pragma unroll
            for (int rr = 0; rr < 4; rr++)
                *(uint4*)&Bd[(lr + rr * 32) * PJ_STRIDE + lc * 4] =
                    make_uint4(f2tf32(sb[rr].x), f2tf32(sb[rr].y),
                               f2tf32(sb[rr].z), f2tf32(sb[rr].w));
        }
        __syncthreads();
    }

    // epilogue: bias + store
#pragma unroll
    for (int mt = 0; mt < 4; mt++) {
        int r0 = i0 + wm * 64 + mt * 16 + gid;
#pragma unroll
        for (int nt = 0; nt < 8; nt++) {
            int c0 = wn * 64 + nt * 8 + 2 * tid4;
            float2 bias = *(const float2*)&Bv[c0];
            float* p0 = &out[(size_t)r0 * 384 + my * 128 + c0];
            float* p1 = &out[(size_t)(r0 + 8) * 384 + my * 128 + c0];
            *(float2*)p0 = make_float2(acc[mt][nt][0] + bias.x,
                                       acc[mt][nt][1] + bias.y);
            *(float2*)p1 = make_float2(acc[mt][nt][2] + bias.x,
                                       acc[mt][nt][3] + bias.y);
        }
    }
}

// ---------------------------------------------------------------------------
// Kernel A2: a[b][t] = sigmoid(dot(x[b][t], k1 - k2))
// ---------------------------------------------------------------------------
__global__ __launch_bounds__(256) void a_gate_kernel(
    const float* __restrict__ x, const float* __restrict__ k1k2,
    float* __restrict__ ga)
{
    const int warp = threadIdx.x >> 5, lane = threadIdx.x & 31;
    const int row = blockIdx.x * 8 + warp;
    const float* xr = x + (size_t)row * 256;
    float s = 0.f;
#pragma unroll
    for (int r = 0; r < 2; r++) {
        int k = lane * 4 + r * 128;
        float4 xv = *(const float4*)&xr[k];
        float4 a1 = *(const float4*)&k1k2[k];
        float4 a2 = *(const float4*)&k1k2[256 + k];
        s += xv.x * (a1.x - a2.x) + xv.y * (a1.y - a2.y) +
             xv.z * (a1.z - a2.z) + xv.w * (a1.w - a2.w);
    }
#pragma unroll
    for (int off = 16; off > 0; off >>= 1)
        s += __shfl_xor_sync(0xffffffffu, s, off);
    if (lane == 0) ga[row] = __fdividef(1.f, 1.f + __expf(-s));
}

// ---------------------------------------------------------------------------
// Kernel B (R5's v4, best measured rnn): 128 CTAs x 2 batches, 256 threads.
// ---------------------------------------------------------------------------
#define MPAR 272   // floats per parity
#define MBAT 136   // floats per batch
#define MHALF 68   // floats per k-half (64 data + 4 pad)

__global__ __launch_bounds__(256, 1) void rnn_kernel(
    const float* __restrict__ gX, const float* __restrict__ ga,
    const int* __restrict__ cor,
    const float* __restrict__ ur, const float* __restrict__ uz,
    const float* __restrict__ uh,
    float* __restrict__ out)
{
    extern __shared__ float sm[];
    float* m_sm   = sm;                    // [2 parity][2 b][2 half][68]  544
    float* a_sm   = sm + 544;              // [2][256]               512
    int*   cor_sm = (int*)(sm + 1056);     // [2][256]               512
    float* buf    = sm + 1568;             // [2][257][64]           32896

    const int tid = threadIdx.x;
    const int q   = tid & 1;
    const int d   = tid >> 1;
    const int b0  = blockIdx.x * 2;
    const int kb  = q * 64;

    unsigned long long urr[32], uzr[32], uhr[32];
#pragma unroll
    for (int j = 0; j < 32; j++) {
        urr[j] = *(const unsigned long long*)&ur[d * 128 + kb + 2 * j];
        uzr[j] = *(const unsigned long long*)&uz[d * 128 + kb + 2 * j];
        uhr[j] = *(const unsigned long long*)&uh[d * 128 + kb + 2 * j];
    }

#pragma unroll
    for (int i = tid; i < 544; i += 256) m_sm[i] = 0.f;
    if (tid < 128) {
        int bb = tid >> 6;
        buf[bb * 16448 + (tid & 63)] = 0.f;
    }
#pragma unroll
    for (int i = tid; i < 512; i += 256) {
        int bb = i >> 8, tt = i & 255;
        a_sm[i]   = ga[(size_t)(b0 + bb) * LL + tt];
        cor_sm[i] = cor[(size_t)(b0 + bb) * LL + tt];
    }
    __syncthreads();

    size_t xbase = ((size_t)(b0 + q) * LL) * 384 + d;
    float xr = gX[xbase], xz = gX[xbase + 128], xh = gX[xbase + 256];

    for (int t = 0; t < LL; t++) {
        const int par = t & 1;
        const int np  = par ^ 1;

        const ulonglong2* p0 =
            (const ulonglong2*)(m_sm + par * MPAR + q * MHALF);
        const ulonglong2* p1 =
            (const ulonglong2*)(m_sm + par * MPAR + MBAT + q * MHALF);
        unsigned long long ar0 = 0ULL, az0 = 0ULL, ah0 = 0ULL;
        unsigned long long ar1 = 0ULL, az1 = 0ULL, ah1 = 0ULL;
#pragma unroll
        for (int j = 0; j < 16; j++) {
            ulonglong2 v0 = p0[j];
            ulonglong2 v1 = p1[j];
            ar0 = ffma2(urr[2*j],   v0.x, ar0);
            az0 = ffma2(uzr[2*j],   v0.x, az0);
            ah0 = ffma2(uhr[2*j],   v0.x, ah0);
            ar1 = ffma2(urr[2*j],   v1.x, ar1);
            az1 = ffma2(uzr[2*j],   v1.x, az1);
            ah1 = ffma2(uhr[2*j],   v1.x, ah1);
            ar0 = ffma2(urr[2*j+1], v0.y, ar0);
            az0 = ffma2(uzr[2*j+1], v0.y, az0);
            ah0 = ffma2(uhr[2*j+1], v0.y, ah0);
            ar1 = ffma2(urr[2*j+1], v1.y, ar1);
            az1 = ffma2(uzr[2*j+1], v1.y, az1);
            ah1 = ffma2(uhr[2*j+1], v1.y, ah1);
        }

        float2 f;
        f = unpack2(ar0); float sr0 = f.x + f.y;
        f = unpack2(az0); float sz0 = f.x + f.y;
        f = unpack2(ah0); float sh0 = f.x + f.y;
        f = unpack2(ar1); float sr1 = f.x + f.y;
        f = unpack2(az1); float sz1 = f.x + f.y;
        f = unpack2(ah1); float sh1 = f.x + f.y;

        float sr = (q ? sr1 : sr0) + __shfl_xor_sync(0xffffffffu, q ? sr0 : sr1, 1);
        float sz = (q ? sz1 : sz0) + __shfl_xor_sync(0xffffffffu, q ? sz0 : sz1, 1);
        float sh = (q ? sh1 : sh0) + __shfl_xor_sync(0xffffffffu, q ? sh0 : sh1, 1);

        float r  = __fdividef(1.f, 1.f + __expf(-(xr + sr)));
        float z  = __fdividef(1.f, 1.f + __expf(-(xz + sz)));
        float ey = __expf(2.f * (xh + r * sh));
        float hv = 1.f - __fdividef(2.f, ey + 1.f);
        float mv = m_sm[par * MPAR + q * MBAT + (d < HH ? d : MHALF + d - HH)];
        float h  = (1.f - z) * mv + z * hv;

        out[(((size_t)(b0 + q) * LL) + t) * DD + d] = h;

        if (t + 1 < LL) {
            xbase = ((size_t)(b0 + q) * LL + (t + 1)) * 384 + d;
            xr = gX[xbase]; xz = gX[xbase + 128]; xh = gX[xbase + 256];

            float an = a_sm[q * 256 + t + 1];
            if (d < HH) {
                m_sm[np * MPAR + q * MBAT + d] = an * h;
            } else {
                buf[q * 16448 + (t + 1) * 64 + (d - HH)] = h;
                int cn = cor_sm[q * 256 + t + 1];
                int ie = (cn == 0) ? (t + 1) : cn;
                m_sm[np * MPAR + q * MBAT + MHALF + (d - HH)] =
                    (1.f - an) * buf[q * 16448 + ie * 64 + (d - HH)];
            }
        }
        __syncthreads();
    }
}

// ---------------------------------------------------------------------------
// launch
// ---------------------------------------------------------------------------
extern "C" void kernel_launch(void* const* d_in, const int* in_sizes, int n_in,
                              void* d_out, int out_size)
{
    (void)in_sizes; (void)n_in; (void)out_size;
    const float* x    = (const float*)d_in[0];
    const int*   cor  = (const int*)d_in[1];
    const float* w_r  = (const float*)d_in[2];
    const float* b_r  = (const float*)d_in[3];
    const float* u_r  = (const float*)d_in[4];
    const float* w_z  = (const float*)d_in[5];
    const float* b_z  = (const float*)d_in[6];
    const float* u_z  = (const float*)d_in[7];
    const float* w_h  = (const float*)d_in[8];
    const float* b_h  = (const float*)d_in[9];
    const float* u_h  = (const float*)d_in[10];
    const float* k1k2 = (const float*)d_in[11];
    float* out = (float*)d_out;

    float* gX; cudaGetSymbolAddress((void**)&gX, g_X);
    float* ga; cudaGetSymbolAddress((void**)&ga, g_a);

    // Kernel A: projections, 64x64 warp tiles (BM=256)
    {
        const int smemA = 2 * (PJ_ATILE + PJ_BTILE) * 4;   // 110592 B
        cudaFuncSetAttribute(proj_gemm_tf32,
                             cudaFuncAttributeMaxDynamicSharedMemorySize, smemA);
        dim3 grid(BB * LL / 256, 3);
        proj_gemm_tf32<<<grid, 256, smemA>>>(x, w_r, b_r, w_z, b_z, w_h, b_h, gX);
    }
    // Kernel A2: attention gate
    a_gate_kernel<<<BB * LL / 8, 256>>>(x, k1k2, ga);

    // Kernel B: recurrence (best measured variant)
    {
        const size_t smemB = (size_t)(544 + 512 + 512 + 2 * 257 * 64)
                             * sizeof(float);            // 137856 B
        cudaFuncSetAttribute(rnn_kernel,
                             cudaFuncAttributeMaxDynamicSharedMemorySize,
                             (int)smemB);
        rnn_kernel<<<128, 256, smemB>>>(gX, ga, cor, u_r, u_z, u_h, out);
    }
}